// round 5
// baseline (speedup 1.0000x reference)
#include <cuda_runtime.h>
#include <cuda_bf16.h>
#include <cstdint>

// ---------------------------------------------------------------------------
// Problem constants
//   V=400000, E=300, H=100, NH=200, N_EDUS=256, T=32, N_ACT=2
// Pipeline:
//   GEMM (emb-gather fused)  -> xproj[8192,800]
//   lstm_rec (per seq,dir)   -> hA[8192,200]
//   GEMM                     -> xproj ; lstm_rec -> hB
//   GEMM                     -> xproj ; lstm_rec -> hA
//   enc = masked mean        -> enc[256,200]
//   parser (single CTA, 511 sequential shift/reduce steps) -> out[200]
// ---------------------------------------------------------------------------

#define NSEQ 256
#define TT   32
#define MTOT (NSEQ*TT)   // 8192
#define GNN  800         // 2 dirs * 400 gates

// Scratch (device globals; no allocations anywhere)
__device__ float g_xproj[MTOT * GNN];   // 26.2 MB
__device__ float g_hA[MTOT * 200];      // 6.55 MB
__device__ float g_hB[MTOT * 200];      // 6.55 MB
__device__ float g_enc[NSEQ * 200];     // 0.2 MB

__device__ __forceinline__ float sigm(float x)   { return 1.0f / (1.0f + __expf(-x)); }
__device__ __forceinline__ float tanh_f(float x) { return 2.0f / (1.0f + __expf(-2.0f * x)) - 1.0f; }

// ---------------------------------------------------------------------------
// SGEMM: g_xproj[m][n] = sum_k A[m][k] * W[n][k]
//   M = 8192 (always), N = 800 (always), K = 300 or 200 (multiple of 4)
//   asel == 0 : A row m = emb + tokens[m]*K   (fused embedding gather)
//   asel == 1 : A = g_hA ; asel == 2 : A = g_hB
// 128x128 tile, BK=8, 256 threads, 8x8 microtile.
// ---------------------------------------------------------------------------
__global__ __launch_bounds__(256, 2) void sgemm_tn(
    int asel, const float* __restrict__ W, int K,
    const int* __restrict__ tokens, const float* __restrict__ emb)
{
    const int N = GNN;
    const int tid  = threadIdx.x;
    const int tx   = tid & 15;
    const int ty   = tid >> 4;
    const int lrow = tid >> 1;          // 0..127
    const int lk   = (tid & 1) << 2;    // 0 or 4
    const int bm   = blockIdx.x * 128;
    const int bn   = blockIdx.y * 128;

    const float* Arow;
    {
        const int m = bm + lrow;        // M divisible by 128, no guard
        if (asel == 0)      Arow = emb + (size_t)tokens[m] * K;
        else if (asel == 1) Arow = g_hA + (size_t)m * K;
        else                Arow = g_hB + (size_t)m * K;
    }
    const int  nrow   = bn + lrow;
    const bool wvalid = (nrow < N);
    const float* Wrow = W + (size_t)(wvalid ? nrow : 0) * K;

    __shared__ float As[8][128];
    __shared__ float Bs[8][128];

    float acc[8][8];
#pragma unroll
    for (int i = 0; i < 8; i++)
#pragma unroll
        for (int j = 0; j < 8; j++) acc[i][j] = 0.0f;

    for (int k0 = 0; k0 < K; k0 += 8) {
        const int ka = k0 + lk;   // multiple of 4; K multiple of 4 -> whole float4 in/out
        float4 av = make_float4(0.f, 0.f, 0.f, 0.f);
        float4 bv = make_float4(0.f, 0.f, 0.f, 0.f);
        if (ka < K)            av = *(const float4*)(Arow + ka);
        if (wvalid && ka < K)  bv = *(const float4*)(Wrow + ka);
        As[lk + 0][lrow] = av.x; As[lk + 1][lrow] = av.y;
        As[lk + 2][lrow] = av.z; As[lk + 3][lrow] = av.w;
        Bs[lk + 0][lrow] = bv.x; Bs[lk + 1][lrow] = bv.y;
        Bs[lk + 2][lrow] = bv.z; Bs[lk + 3][lrow] = bv.w;
        __syncthreads();

#pragma unroll
        for (int kk = 0; kk < 8; kk++) {
            float a[8], b[8];
            *(float4*)&a[0] = *(const float4*)&As[kk][ty * 8];
            *(float4*)&a[4] = *(const float4*)&As[kk][ty * 8 + 4];
            *(float4*)&b[0] = *(const float4*)&Bs[kk][tx * 8];
            *(float4*)&b[4] = *(const float4*)&Bs[kk][tx * 8 + 4];
#pragma unroll
            for (int i = 0; i < 8; i++)
#pragma unroll
                for (int j = 0; j < 8; j++) acc[i][j] += a[i] * b[j];
        }
        __syncthreads();
    }

#pragma unroll
    for (int i = 0; i < 8; i++) {
        const int m = bm + ty * 8 + i;
        float* crow = g_xproj + (size_t)m * N;
#pragma unroll
        for (int j = 0; j < 8; j++) {
            const int n = bn + tx * 8 + j;
            if (n < N) crow[n] = acc[i][j];
        }
    }
}

// ---------------------------------------------------------------------------
// LSTM recurrence: one block per (sequence, direction). 512 blocks.
// Whh row (100 floats) lives in registers of gate-thread g (g<400).
// Exact masking semantics of the reference:
//   valid = t < len ; carry updated iff valid ; output = valid ? hn : 0
// ---------------------------------------------------------------------------
__global__ __launch_bounds__(416, 1) void lstm_rec(
    const float* __restrict__ Whh, const float* __restrict__ bias,
    const int* __restrict__ lengths, int osel)
{
    const int b = blockIdx.x >> 1;
    const int d = blockIdx.x & 1;
    const int g = threadIdx.x;

    float* out = osel ? g_hB : g_hA;

    __shared__ __align__(16) float h_s[100];
    __shared__ float gates_s[400];

    float wreg[100];
    float bias_r = 0.0f;
    if (g < 400) {
        const float* wp = Whh + (size_t)(d * 400 + g) * 100;
#pragma unroll
        for (int k = 0; k < 100; k += 4) {
            float4 w = *(const float4*)(wp + k);
            wreg[k] = w.x; wreg[k + 1] = w.y; wreg[k + 2] = w.z; wreg[k + 3] = w.w;
        }
        bias_r = bias[d * 400 + g];
    }
    if (g < 100) h_s[g] = 0.0f;
    float c_r = 0.0f;
    const int len = lengths[b];
    __syncthreads();

    for (int s = 0; s < 32; s++) {
        const int t = d ? (31 - s) : s;
        if (g < 400) {
            float acc = g_xproj[(size_t)(b * 32 + t) * 800 + d * 400 + g] + bias_r;
#pragma unroll
            for (int k = 0; k < 100; k += 4) {
                float4 hv = *(const float4*)(h_s + k);
                acc += wreg[k] * hv.x + wreg[k + 1] * hv.y
                     + wreg[k + 2] * hv.z + wreg[k + 3] * hv.w;
            }
            gates_s[g] = acc;
        }
        __syncthreads();
        if (g < 100) {
            const bool valid = (t < len);
            const float iv = gates_s[g];
            const float fv = gates_s[100 + g];
            const float gv = gates_s[200 + g];
            const float ov = gates_s[300 + g];
            const float cn = sigm(fv) * c_r + sigm(iv) * tanh_f(gv);
            const float hn = sigm(ov) * tanh_f(cn);
            const float ho = valid ? hn : h_s[g];
            c_r = valid ? cn : c_r;
            out[(size_t)(b * 32 + t) * 200 + d * 100 + g] = valid ? hn : 0.0f;
            h_s[g] = ho;
        }
        __syncthreads();
    }
}

// ---------------------------------------------------------------------------
// enc[b][g] = (sum_t hA[b][t][g]) / len[b]   (invalid timesteps are already 0)
// ---------------------------------------------------------------------------
__global__ void enc_kernel(const int* __restrict__ lengths)
{
    const int b = blockIdx.x;
    const int g = threadIdx.x;
    if (g < 200) {
        float s = 0.0f;
#pragma unroll
        for (int t = 0; t < 32; t++) s += g_hA[(size_t)(b * 32 + t) * 200 + g];
        g_enc[b * 200 + g] = s / (float)lengths[b];
    }
}

// ---------------------------------------------------------------------------
// Shift-reduce parser: single CTA, 512 threads, 511 sequential steps.
// Stack (256x200 f32 = 204.8 KB) in dynamic smem. Wt streamed from L2 only
// on reduce steps. Decision is exactly argmax(where(legal, scores, -1e30))==0
// i.e. shift iff m0 >= m1 (argmax tie -> index 0).
// ---------------------------------------------------------------------------
__global__ __launch_bounds__(512, 1) void parser_kernel(
    const float* __restrict__ missing,
    const float* __restrict__ Wa, const float* __restrict__ ba,
    const float* __restrict__ Wt, const float* __restrict__ bt,
    float* __restrict__ out)
{
    extern __shared__ float sm[];
    float* stack = sm;                 // 256*200 = 51200
    float* feat  = sm + 51200;         // 600
    float* u_s   = feat + 600;         // 200
    float* gat   = u_s + 200;          // 500
    float* wa_s  = gat + 500;          // 1200
    float* bt_s  = wa_s + 1200;        // 500
    __shared__ int   dec_s;
    __shared__ float ba_s[2];

    const int t = threadIdx.x;
    for (int i = t; i < 1200; i += 512) wa_s[i] = Wa[i];
    for (int i = t; i < 500;  i += 512) bt_s[i] = bt[i];
    if (t < 2) ba_s[t] = ba[t];

    int sp = 0, bp = 0;
    __syncthreads();

    for (int step = 0; step < 2 * NSEQ - 1; step++) {
        // feat = [s1 ; s0 ; b]  (missing-vector substitution per reference)
        for (int i = t; i < 600; i += 512) {
            float v;
            if (i < 200)       v = (sp >= 2) ? stack[(sp - 2) * 200 + i]         : missing[i];
            else if (i < 400)  v = (sp >= 1) ? stack[(sp - 1) * 200 + (i - 200)] : missing[i - 200];
            else               v = (bp < NSEQ) ? g_enc[(size_t)bp * 200 + (i - 400)] : missing[i - 400];
            feat[i] = v;
        }
        __syncthreads();

        // scores = Wa @ feat + ba ; legality mask ; decision (warp 0)
        if (t < 32) {
            float a0 = 0.0f, a1 = 0.0f;
            for (int k = t; k < 600; k += 32) {
                const float f = feat[k];
                a0 += wa_s[k] * f;
                a1 += wa_s[600 + k] * f;
            }
#pragma unroll
            for (int o = 16; o > 0; o >>= 1) {
                a0 += __shfl_xor_sync(0xffffffffu, a0, o);
                a1 += __shfl_xor_sync(0xffffffffu, a1, o);
            }
            if (t == 0) {
                const float m0 = (bp < NSEQ) ? (a0 + ba_s[0]) : -1e30f;
                const float m1 = (sp >= 2)   ? (a1 + ba_s[1]) : -1e30f;
                dec_s = (m0 >= m1) ? 1 : 0;
            }
        }
        __syncthreads();

        const int isShift = dec_s;   // block-uniform
        if (isShift) {
            int pos = sp; if (pos > NSEQ - 1) pos = NSEQ - 1;
            if (t < 200) stack[pos * 200 + t] = feat[400 + t];
            sp += 1; bp += 1;
        } else {
            // tree-LSTM input: [h1 ; h2] = [s1[0:100] ; s0[0:100]]
            if (t < 200) u_s[t] = (t < 100) ? feat[t] : feat[100 + t];
            __syncthreads();
            if (t < 500) {
                const float* wr = Wt + (size_t)t * 200;
                float acc = bt_s[t];
#pragma unroll
                for (int k = 0; k < 200; k += 4) {
                    const float4 wv = *(const float4*)(wr + k);
                    const float4 uv = *(const float4*)(u_s + k);
                    acc += wv.x * uv.x + wv.y * uv.y + wv.z * uv.z + wv.w * uv.w;
                }
                gat[t] = acc;
            }
            __syncthreads();
            if (t < 100) {
                const float iv = gat[t];
                const float f1 = gat[100 + t];
                const float f2 = gat[200 + t];
                const float ov = gat[300 + t];
                const float uu = gat[400 + t];
                const float c1 = feat[100 + t];   // s1 cell half
                const float c2 = feat[300 + t];   // s0 cell half
                const float c  = sigm(f1) * c1 + sigm(f2) * c2 + sigm(iv) * tanh_f(uu);
                const float h  = sigm(ov) * tanh_f(c);
                int pos = sp - 2; if (pos < 0) pos = 0;
                stack[pos * 200 + t]       = h;
                stack[pos * 200 + 100 + t] = c;
            }
            sp -= 1;
        }
        __syncthreads();
    }

    if (t < 200) out[t] = stack[t];
}

// ---------------------------------------------------------------------------
// Host launcher
// ---------------------------------------------------------------------------
extern "C" void kernel_launch(void* const* d_in, const int* in_sizes, int n_in,
                              void* d_out, int out_size)
{
    const int*   tokens  = (const int*)  d_in[0];   // (256,32)
    const int*   lengths = (const int*)  d_in[1];   // (256,)
    const float* emb     = (const float*)d_in[2];   // (400000,300)
    const float* Wih_l0  = (const float*)d_in[3];   // (2,400,300)
    const float* Whh_l0  = (const float*)d_in[4];   // (2,400,100)
    const float* b_l0    = (const float*)d_in[5];   // (2,400)
    const float* Wih_l12 = (const float*)d_in[6];   // (2,2,400,200)
    const float* Whh_l12 = (const float*)d_in[7];   // (2,2,400,100)
    const float* b_l12   = (const float*)d_in[8];   // (2,2,400)
    const float* missing = (const float*)d_in[9];   // (200,)
    const float* Wa      = (const float*)d_in[10];  // (2,600)
    const float* ba      = (const float*)d_in[11];  // (2,)
    const float* Wt      = (const float*)d_in[12];  // (500,200)
    const float* bt      = (const float*)d_in[13];  // (500,)
    float* out = (float*)d_out;

    const size_t parser_smem = (51200 + 600 + 200 + 500 + 1200 + 500) * sizeof(float); // 216.8 KB
    cudaFuncSetAttribute(parser_kernel, cudaFuncAttributeMaxDynamicSharedMemorySize,
                         (int)parser_smem);

    const dim3 gg(MTOT / 128, (GNN + 127) / 128);   // (64, 7)

    // Layer 0: fused gather GEMM (K=300) + recurrence -> hA
    sgemm_tn<<<gg, 256>>>(0, Wih_l0, 300, tokens, emb);
    lstm_rec<<<2 * NSEQ, 416>>>(Whh_l0, b_l0, lengths, /*osel hA*/ 0);

    // Layer 1: GEMM on hA (K=200) + recurrence -> hB
    sgemm_tn<<<gg, 256>>>(1, Wih_l12, 200, nullptr, nullptr);
    lstm_rec<<<2 * NSEQ, 416>>>(Whh_l12, b_l12, lengths, /*osel hB*/ 1);

    // Layer 2: GEMM on hB (K=200) + recurrence -> hA
    sgemm_tn<<<gg, 256>>>(2, Wih_l12 + 2 * 400 * 200, 200, nullptr, nullptr);
    lstm_rec<<<2 * NSEQ, 416>>>(Whh_l12 + 2 * 400 * 100, b_l12 + 800, lengths, /*osel hA*/ 0);

    // Masked mean over time
    enc_kernel<<<NSEQ, 256>>>(lengths);

    // Sequential shift-reduce parse
    parser_kernel<<<1, 512, parser_smem>>>(missing, Wa, ba, Wt, bt, out);
}

// round 9
// speedup vs baseline: 3.9692x; 3.9692x over previous
#include <cuda_runtime.h>
#include <cuda_bf16.h>
#include <cstdint>

// ---------------------------------------------------------------------------
// Problem constants
//   V=400000, E=300, H=100, NH=200, N_EDUS=256, T=32, N_ACT=2
// Pipeline:
//   GEMM (emb-gather fused)  -> xproj[8192,800]
//   lstm_rec (per seq,dir)   -> hA[8192,200]
//   GEMM                     -> xproj ; lstm_rec -> hB
//   GEMM                     -> xproj ; lstm_rec -> hA
//   enc = masked mean        -> enc[256,200]
//   parser: 8-CTA cluster, Wt distributed across worker CTAs' smem,
//           511 sequential steps coordinated with barrier.cluster -> out[200]
// ---------------------------------------------------------------------------

#define NSEQ 256
#define TT   32
#define MTOT (NSEQ*TT)   // 8192
#define GNN  800         // 2 dirs * 400 gates

// Scratch (device globals; no allocations anywhere)
__device__ float g_xproj[MTOT * GNN];   // 26.2 MB
__device__ float g_hA[MTOT * 200];      // 6.55 MB
__device__ float g_hB[MTOT * 200];      // 6.55 MB
__device__ float g_enc[NSEQ * 200];     // 0.2 MB

__device__ __forceinline__ float sigm(float x)   { return 1.0f / (1.0f + __expf(-x)); }
__device__ __forceinline__ float tanh_f(float x) { return 2.0f / (1.0f + __expf(-2.0f * x)) - 1.0f; }

// ---------------------------------------------------------------------------
// SGEMM: g_xproj[m][n] = sum_k A[m][k] * W[n][k]   (unchanged from R5 pass)
// ---------------------------------------------------------------------------
__global__ __launch_bounds__(256, 2) void sgemm_tn(
    int asel, const float* __restrict__ W, int K,
    const int* __restrict__ tokens, const float* __restrict__ emb)
{
    const int N = GNN;
    const int tid  = threadIdx.x;
    const int tx   = tid & 15;
    const int ty   = tid >> 4;
    const int lrow = tid >> 1;
    const int lk   = (tid & 1) << 2;
    const int bm   = blockIdx.x * 128;
    const int bn   = blockIdx.y * 128;

    const float* Arow;
    {
        const int m = bm + lrow;
        if (asel == 0)      Arow = emb + (size_t)tokens[m] * K;
        else if (asel == 1) Arow = g_hA + (size_t)m * K;
        else                Arow = g_hB + (size_t)m * K;
    }
    const int  nrow   = bn + lrow;
    const bool wvalid = (nrow < N);
    const float* Wrow = W + (size_t)(wvalid ? nrow : 0) * K;

    __shared__ float As[8][128];
    __shared__ float Bs[8][128];

    float acc[8][8];
#pragma unroll
    for (int i = 0; i < 8; i++)
#pragma unroll
        for (int j = 0; j < 8; j++) acc[i][j] = 0.0f;

    for (int k0 = 0; k0 < K; k0 += 8) {
        const int ka = k0 + lk;
        float4 av = make_float4(0.f, 0.f, 0.f, 0.f);
        float4 bv = make_float4(0.f, 0.f, 0.f, 0.f);
        if (ka < K)            av = *(const float4*)(Arow + ka);
        if (wvalid && ka < K)  bv = *(const float4*)(Wrow + ka);
        As[lk + 0][lrow] = av.x; As[lk + 1][lrow] = av.y;
        As[lk + 2][lrow] = av.z; As[lk + 3][lrow] = av.w;
        Bs[lk + 0][lrow] = bv.x; Bs[lk + 1][lrow] = bv.y;
        Bs[lk + 2][lrow] = bv.z; Bs[lk + 3][lrow] = bv.w;
        __syncthreads();

#pragma unroll
        for (int kk = 0; kk < 8; kk++) {
            float a[8], b[8];
            *(float4*)&a[0] = *(const float4*)&As[kk][ty * 8];
            *(float4*)&a[4] = *(const float4*)&As[kk][ty * 8 + 4];
            *(float4*)&b[0] = *(const float4*)&Bs[kk][tx * 8];
            *(float4*)&b[4] = *(const float4*)&Bs[kk][tx * 8 + 4];
#pragma unroll
            for (int i = 0; i < 8; i++)
#pragma unroll
                for (int j = 0; j < 8; j++) acc[i][j] += a[i] * b[j];
        }
        __syncthreads();
    }

#pragma unroll
    for (int i = 0; i < 8; i++) {
        const int m = bm + ty * 8 + i;
        float* crow = g_xproj + (size_t)m * N;
#pragma unroll
        for (int j = 0; j < 8; j++) {
            const int n = bn + tx * 8 + j;
            if (n < N) crow[n] = acc[i][j];
        }
    }
}

// ---------------------------------------------------------------------------
// LSTM recurrence (unchanged from R5 pass)
// ---------------------------------------------------------------------------
__global__ __launch_bounds__(416, 1) void lstm_rec(
    const float* __restrict__ Whh, const float* __restrict__ bias,
    const int* __restrict__ lengths, int osel)
{
    const int b = blockIdx.x >> 1;
    const int d = blockIdx.x & 1;
    const int g = threadIdx.x;

    float* out = osel ? g_hB : g_hA;

    __shared__ __align__(16) float h_s[100];
    __shared__ float gates_s[400];

    float wreg[100];
    float bias_r = 0.0f;
    if (g < 400) {
        const float* wp = Whh + (size_t)(d * 400 + g) * 100;
#pragma unroll
        for (int k = 0; k < 100; k += 4) {
            float4 w = *(const float4*)(wp + k);
            wreg[k] = w.x; wreg[k + 1] = w.y; wreg[k + 2] = w.z; wreg[k + 3] = w.w;
        }
        bias_r = bias[d * 400 + g];
    }
    if (g < 100) h_s[g] = 0.0f;
    float c_r = 0.0f;
    const int len = lengths[b];
    __syncthreads();

    for (int s = 0; s < 32; s++) {
        const int t = d ? (31 - s) : s;
        if (g < 400) {
            float acc = g_xproj[(size_t)(b * 32 + t) * 800 + d * 400 + g] + bias_r;
#pragma unroll
            for (int k = 0; k < 100; k += 4) {
                float4 hv = *(const float4*)(h_s + k);
                acc += wreg[k] * hv.x + wreg[k + 1] * hv.y
                     + wreg[k + 2] * hv.z + wreg[k + 3] * hv.w;
            }
            gates_s[g] = acc;
        }
        __syncthreads();
        if (g < 100) {
            const bool valid = (t < len);
            const float iv = gates_s[g];
            const float fv = gates_s[100 + g];
            const float gv = gates_s[200 + g];
            const float ov = gates_s[300 + g];
            const float cn = sigm(fv) * c_r + sigm(iv) * tanh_f(gv);
            const float hn = sigm(ov) * tanh_f(cn);
            const float ho = valid ? hn : h_s[g];
            c_r = valid ? cn : c_r;
            out[(size_t)(b * 32 + t) * 200 + d * 100 + g] = valid ? hn : 0.0f;
            h_s[g] = ho;
        }
        __syncthreads();
    }
}

// ---------------------------------------------------------------------------
// enc[b][g] = (sum_t hA[b][t][g]) / len[b]
// ---------------------------------------------------------------------------
__global__ void enc_kernel(const int* __restrict__ lengths)
{
    const int b = blockIdx.x;
    const int g = threadIdx.x;
    if (g < 200) {
        float s = 0.0f;
#pragma unroll
        for (int t = 0; t < 32; t++) s += g_hA[(size_t)(b * 32 + t) * 200 + g];
        g_enc[b * 200 + g] = s / (float)lengths[b];
    }
}

// ---------------------------------------------------------------------------
// Cluster parser.
//   rank 0 (leader): stack + feat + decision + cell update.
//   ranks 1..7 (workers): hold 72 Wt rows each (padded to 204 floats,
//   conflict-free LDS.128), do the tree-LSTM matvec on reduce steps.
// Dynamic smem layout is by float-offset, identical across CTAs (required
// for mapa-based DSMEM addressing).
// ---------------------------------------------------------------------------
#define P_NW      7
#define P_RPW     72                      // rows per worker (last has 68)
#define OFF_STACK 0                       // 256*200
#define OFF_FEAT  51200                   // 600
#define OFF_GAT   51800                   // 512 (500 used)
#define OFF_U     52312                   // 200
#define OFF_WA    52512                   // 1200
#define OFF_MISS  53712                   // 200
#define OFF_DEC   53912                   // 1 int
#define PAR_SMEM_FLOATS 53916
// worker-local aliases (inside the same allocation, low offsets)
#define WOFF_WT   0                       // 72*204 = 14688
#define WOFF_BT   14688                   // 72
#define WOFF_UL   14760                   // 204 (16B aligned: 14760*4 % 16 == 0)
#define WOFF_DEC  14964                   // 1 int

__device__ __forceinline__ uint32_t smem_addr_u32(const void* p) {
    uint32_t a;
    asm("{ .reg .u64 t; cvta.to.shared.u64 t, %1; cvt.u32.u64 %0, t; }"
        : "=r"(a) : "l"(p));
    return a;
}
__device__ __forceinline__ uint32_t mapa_rank0(uint32_t local) {
    uint32_t r;
    asm("mapa.shared::cluster.u32 %0, %1, 0;" : "=r"(r) : "r"(local));
    return r;
}
__device__ __forceinline__ float ld_dsmem_f(uint32_t a) {
    float v;
    asm volatile("ld.shared::cluster.f32 %0, [%1];" : "=f"(v) : "r"(a));
    return v;
}
__device__ __forceinline__ int ld_dsmem_i(uint32_t a) {
    int v;
    asm volatile("ld.shared::cluster.b32 %0, [%1];" : "=r"(v) : "r"(a));
    return v;
}
__device__ __forceinline__ void st_dsmem_f(uint32_t a, float v) {
    asm volatile("st.shared::cluster.f32 [%0], %1;" :: "r"(a), "f"(v) : "memory");
}
__device__ __forceinline__ void cluster_sync_all() {
    asm volatile("barrier.cluster.arrive.aligned;" ::: "memory");
    asm volatile("barrier.cluster.wait.aligned;"   ::: "memory");
}

__global__ __launch_bounds__(512, 1) __cluster_dims__(8, 1, 1)
void parser_kernel(
    const float* __restrict__ missing,
    const float* __restrict__ Wa, const float* __restrict__ ba,
    const float* __restrict__ Wt, const float* __restrict__ bt,
    float* __restrict__ out)
{
    extern __shared__ float sm[];
    const int t    = threadIdx.x;
    const int rank = blockIdx.x;           // grid == one cluster of 8
    __shared__ float ba_s[2];

    float* stack = sm + OFF_STACK;
    float* feat  = sm + OFF_FEAT;
    float* gat   = sm + OFF_GAT;
    float* u_s   = sm + OFF_U;
    float* wa_s  = sm + OFF_WA;
    float* mis_s = sm + OFF_MISS;

    int wbase = 0, wcnt = 0;
    if (rank == 0) {
        for (int i = t; i < 1200; i += 512) wa_s[i]  = Wa[i];
        for (int i = t; i < 200;  i += 512) mis_s[i] = missing[i];
        if (t < 2) ba_s[t] = ba[t];
    } else {
        wbase = (rank - 1) * P_RPW;
        wcnt  = min(P_RPW, 500 - wbase);
        for (int i = t; i < wcnt * 200; i += 512) {
            const int r = i / 200, k = i % 200;
            sm[WOFF_WT + r * 204 + k] = Wt[(size_t)(wbase + r) * 200 + k];
        }
        for (int i = t; i < wcnt; i += 512) sm[WOFF_BT + i] = bt[wbase + i];
    }
    __syncthreads();
    cluster_sync_all();

    int sp = 0, bp = 0;
    int isShift = 0;

    for (int step = 0; step < 2 * NSEQ - 1; step++) {
        // ---------------- Phase A: leader computes feat, decision, publishes
        if (rank == 0) {
            for (int i = t; i < 600; i += 512) {
                float v;
                if (i < 200)      v = (sp >= 2) ? stack[(sp - 2) * 200 + i]         : mis_s[i];
                else if (i < 400) v = (sp >= 1) ? stack[(sp - 1) * 200 + (i - 200)] : mis_s[i - 200];
                else              v = (bp < NSEQ) ? g_enc[(size_t)bp * 200 + (i - 400)] : mis_s[i - 400];
                feat[i] = v;
            }
            __syncthreads();

            if (t < 32) {
                float a0 = 0.0f, a1 = 0.0f;
                for (int k = t; k < 600; k += 32) {
                    const float f = feat[k];
                    a0 += wa_s[k] * f;
                    a1 += wa_s[600 + k] * f;
                }
#pragma unroll
                for (int o = 16; o > 0; o >>= 1) {
                    a0 += __shfl_xor_sync(0xffffffffu, a0, o);
                    a1 += __shfl_xor_sync(0xffffffffu, a1, o);
                }
                if (t == 0) {
                    const float m0 = (bp < NSEQ) ? (a0 + ba_s[0]) : -1e30f;
                    const float m1 = (sp >= 2)   ? (a1 + ba_s[1]) : -1e30f;
                    ((int*)sm)[OFF_DEC] = (m0 >= m1) ? 1 : 0;   // argmax tie -> shift
                }
            }
            __syncthreads();

            isShift = ((const int*)sm)[OFF_DEC];
            if (isShift) {
                int pos = sp; if (pos > NSEQ - 1) pos = NSEQ - 1;
                if (t < 200) stack[pos * 200 + t] = feat[400 + t];
                sp += 1; bp += 1;
            } else {
                if (t < 200) u_s[t] = (t < 100) ? feat[t] : feat[100 + t];  // [h1;h2]
                sp -= 1;
            }
        }

        cluster_sync_all();   // publishes dec/u to workers (release/acquire)

        // ---------------- Phase B: workers do the distributed matvec
        if (rank != 0) {
            if (t == 0)
                ((int*)sm)[WOFF_DEC] = ld_dsmem_i(mapa_rank0(smem_addr_u32(&((int*)sm)[OFF_DEC])));
            if (t < 200)
                sm[WOFF_UL + t] = ld_dsmem_f(mapa_rank0(smem_addr_u32(&u_s[t])));
            __syncthreads();
            const int red = (((const int*)sm)[WOFF_DEC] == 0);
            if (red && t < wcnt) {
                const float* wr = sm + WOFF_WT + t * 204;
                const float* ul = sm + WOFF_UL;
                float a0 = 0.f, a1 = 0.f, a2 = 0.f, a3 = 0.f;
#pragma unroll
                for (int k = 0; k < 200; k += 4) {
                    const float4 wv = *(const float4*)(wr + k);
                    const float4 uv = *(const float4*)(ul + k);
                    a0 += wv.x * uv.x; a1 += wv.y * uv.y;
                    a2 += wv.z * uv.z; a3 += wv.w * uv.w;
                }
                const float acc = sm[WOFF_BT + t] + ((a0 + a1) + (a2 + a3));
                st_dsmem_f(mapa_rank0(smem_addr_u32(&gat[wbase + t])), acc);
            }
            __syncthreads();
        }

        cluster_sync_all();   // gates visible to leader

        // ---------------- Phase C: leader finishes the reduce
        if (rank == 0) {
            if (!isShift && t < 100) {
                const float iv = gat[t];
                const float f1 = gat[100 + t];
                const float f2 = gat[200 + t];
                const float ov = gat[300 + t];
                const float uu = gat[400 + t];
                const float c1 = feat[100 + t];   // s1 cell half
                const float c2 = feat[300 + t];   // s0 cell half
                const float c  = sigm(f1) * c1 + sigm(f2) * c2 + sigm(iv) * tanh_f(uu);
                const float h  = sigm(ov) * tanh_f(c);
                int pos = sp - 1; if (pos < 0) pos = 0;   // sp already decremented: write at old sp-2
                stack[pos * 200 + t]       = h;
                stack[pos * 200 + 100 + t] = c;
            }
            __syncthreads();   // stack ready for next step's feat gather
        }
    }

    if (rank == 0 && t < 200) out[t] = stack[t];
}

// ---------------------------------------------------------------------------
// Host launcher
// ---------------------------------------------------------------------------
extern "C" void kernel_launch(void* const* d_in, const int* in_sizes, int n_in,
                              void* d_out, int out_size)
{
    const int*   tokens  = (const int*)  d_in[0];
    const int*   lengths = (const int*)  d_in[1];
    const float* emb     = (const float*)d_in[2];
    const float* Wih_l0  = (const float*)d_in[3];
    const float* Whh_l0  = (const float*)d_in[4];
    const float* b_l0    = (const float*)d_in[5];
    const float* Wih_l12 = (const float*)d_in[6];
    const float* Whh_l12 = (const float*)d_in[7];
    const float* b_l12   = (const float*)d_in[8];
    const float* missing = (const float*)d_in[9];
    const float* Wa      = (const float*)d_in[10];
    const float* ba      = (const float*)d_in[11];
    const float* Wt      = (const float*)d_in[12];
    const float* bt      = (const float*)d_in[13];
    float* out = (float*)d_out;

    const size_t parser_smem = PAR_SMEM_FLOATS * sizeof(float);  // 215,664 B
    cudaFuncSetAttribute(parser_kernel, cudaFuncAttributeMaxDynamicSharedMemorySize,
                         (int)parser_smem);

    const dim3 gg(MTOT / 128, (GNN + 127) / 128);   // (64, 7)

    sgemm_tn<<<gg, 256>>>(0, Wih_l0, 300, tokens, emb);
    lstm_rec<<<2 * NSEQ, 416>>>(Whh_l0, b_l0, lengths, 0);

    sgemm_tn<<<gg, 256>>>(1, Wih_l12, 200, nullptr, nullptr);
    lstm_rec<<<2 * NSEQ, 416>>>(Whh_l12, b_l12, lengths, 1);

    sgemm_tn<<<gg, 256>>>(2, Wih_l12 + 2 * 400 * 200, 200, nullptr, nullptr);
    lstm_rec<<<2 * NSEQ, 416>>>(Whh_l12 + 2 * 400 * 100, b_l12 + 800, lengths, 0);

    enc_kernel<<<NSEQ, 256>>>(lengths);

    parser_kernel<<<8, 512, parser_smem>>>(missing, Wa, ba, Wt, bt, out);
}

// round 10
// speedup vs baseline: 4.5567x; 1.1480x over previous
#include <cuda_runtime.h>
#include <cuda_bf16.h>
#include <cstdint>

// ---------------------------------------------------------------------------
// Problem constants
//   V=400000, E=300, H=100, NH=200, N_EDUS=256, T=32, N_ACT=2
// Pipeline:
//   GEMM (emb-gather fused, double-buffered) -> xproj[8192,800]
//   lstm_rec (multi-acc + x-prefetch)        -> hA / hB
//   enc = masked mean                        -> enc[256,200]
//   parser: 8-CTA cluster, Wt distributed; leader pushes u, workers compute
//           tree-LSTM matvec speculatively, overlapped with decision.
// ---------------------------------------------------------------------------

#define NSEQ 256
#define TT   32
#define MTOT (NSEQ*TT)   // 8192
#define GNN  800         // 2 dirs * 400 gates

__device__ float g_xproj[MTOT * GNN];   // 26.2 MB
__device__ float g_hA[MTOT * 200];      // 6.55 MB
__device__ float g_hB[MTOT * 200];      // 6.55 MB
__device__ float g_enc[NSEQ * 200];     // 0.2 MB

__device__ __forceinline__ float sigm(float x)   { return 1.0f / (1.0f + __expf(-x)); }
__device__ __forceinline__ float tanh_f(float x) { return 2.0f / (1.0f + __expf(-2.0f * x)) - 1.0f; }

// ---------------------------------------------------------------------------
// SGEMM: g_xproj[m][n] = sum_k A[m][k] * W[n][k]
// 128x128 tile, BK=8, 256 threads, 8x8 microtile, DOUBLE-BUFFERED smem
// (register-staged prefetch, one __syncthreads per K-iter).
// ---------------------------------------------------------------------------
__global__ __launch_bounds__(256, 2) void sgemm_tn(
    int asel, const float* __restrict__ W, int K,
    const int* __restrict__ tokens, const float* __restrict__ emb)
{
    const int N = GNN;
    const int tid  = threadIdx.x;
    const int tx   = tid & 15;
    const int ty   = tid >> 4;
    const int lrow = tid >> 1;          // 0..127
    const int lk   = (tid & 1) << 2;    // 0 or 4
    const int bm   = blockIdx.x * 128;
    const int bn   = blockIdx.y * 128;

    const float* Arow;
    {
        const int m = bm + lrow;
        if (asel == 0)      Arow = emb + (size_t)tokens[m] * K;
        else if (asel == 1) Arow = g_hA + (size_t)m * K;
        else                Arow = g_hB + (size_t)m * K;
    }
    const int  nrow   = bn + lrow;
    const bool wvalid = (nrow < N);
    const float* Wrow = W + (size_t)(wvalid ? nrow : 0) * K;

    __shared__ float As[2][8][128];
    __shared__ float Bs[2][8][128];

    float acc[8][8];
#pragma unroll
    for (int i = 0; i < 8; i++)
#pragma unroll
        for (int j = 0; j < 8; j++) acc[i][j] = 0.0f;

    // Prologue: load k0 = 0 into buffer 0
    {
        const int ka = lk;
        float4 av = make_float4(0.f, 0.f, 0.f, 0.f);
        float4 bv = make_float4(0.f, 0.f, 0.f, 0.f);
        if (ka < K)            av = *(const float4*)(Arow + ka);
        if (wvalid && ka < K)  bv = *(const float4*)(Wrow + ka);
        As[0][lk + 0][lrow] = av.x; As[0][lk + 1][lrow] = av.y;
        As[0][lk + 2][lrow] = av.z; As[0][lk + 3][lrow] = av.w;
        Bs[0][lk + 0][lrow] = bv.x; Bs[0][lk + 1][lrow] = bv.y;
        Bs[0][lk + 2][lrow] = bv.z; Bs[0][lk + 3][lrow] = bv.w;
    }
    __syncthreads();

    int buf = 0;
    for (int k0 = 0; k0 < K; k0 += 8) {
        // Prefetch next tile into registers (overlaps with compute below)
        float4 av2 = make_float4(0.f, 0.f, 0.f, 0.f);
        float4 bv2 = make_float4(0.f, 0.f, 0.f, 0.f);
        const bool more = (k0 + 8 < K);
        if (more) {
            const int kn = k0 + 8 + lk;
            if (kn < K)            av2 = *(const float4*)(Arow + kn);
            if (wvalid && kn < K)  bv2 = *(const float4*)(Wrow + kn);
        }

#pragma unroll
        for (int kk = 0; kk < 8; kk++) {
            float a[8], b[8];
            *(float4*)&a[0] = *(const float4*)&As[buf][kk][ty * 8];
            *(float4*)&a[4] = *(const float4*)&As[buf][kk][ty * 8 + 4];
            *(float4*)&b[0] = *(const float4*)&Bs[buf][kk][tx * 8];
            *(float4*)&b[4] = *(const float4*)&Bs[buf][kk][tx * 8 + 4];
#pragma unroll
            for (int i = 0; i < 8; i++)
#pragma unroll
                for (int j = 0; j < 8; j++) acc[i][j] += a[i] * b[j];
        }

        if (more) {
            const int nb = buf ^ 1;
            As[nb][lk + 0][lrow] = av2.x; As[nb][lk + 1][lrow] = av2.y;
            As[nb][lk + 2][lrow] = av2.z; As[nb][lk + 3][lrow] = av2.w;
            Bs[nb][lk + 0][lrow] = bv2.x; Bs[nb][lk + 1][lrow] = bv2.y;
            Bs[nb][lk + 2][lrow] = bv2.z; Bs[nb][lk + 3][lrow] = bv2.w;
        }
        __syncthreads();
        buf ^= 1;
    }

#pragma unroll
    for (int i = 0; i < 8; i++) {
        const int m = bm + ty * 8 + i;
        float* crow = g_xproj + (size_t)m * N;
#pragma unroll
        for (int j = 0; j < 8; j++) {
            const int n = bn + tx * 8 + j;
            if (n < N) crow[n] = acc[i][j];
        }
    }
}

// ---------------------------------------------------------------------------
// LSTM recurrence: one block per (sequence, direction). 512 blocks.
// Whh row in registers; 4 independent accumulators (100-cyc chain instead of
// 400); next timestep's gate preactivation prefetched before the matvec.
// ---------------------------------------------------------------------------
__global__ __launch_bounds__(416, 1) void lstm_rec(
    const float* __restrict__ Whh, const float* __restrict__ bias,
    const int* __restrict__ lengths, int osel)
{
    const int b = blockIdx.x >> 1;
    const int d = blockIdx.x & 1;
    const int g = threadIdx.x;

    float* out = osel ? g_hB : g_hA;

    __shared__ __align__(16) float h_s[100];
    __shared__ float gates_s[400];

    float wreg[100];
    float bias_r = 0.0f;
    const float* xcol = g_xproj + (size_t)b * 32 * 800 + d * 400 + g;
    if (g < 400) {
        const float* wp = Whh + (size_t)(d * 400 + g) * 100;
#pragma unroll
        for (int k = 0; k < 100; k += 4) {
            float4 w = *(const float4*)(wp + k);
            wreg[k] = w.x; wreg[k + 1] = w.y; wreg[k + 2] = w.z; wreg[k + 3] = w.w;
        }
        bias_r = bias[d * 400 + g];
    }
    if (g < 100) h_s[g] = 0.0f;
    float c_r = 0.0f;
    const int len = lengths[b];

    // Prefetch x for step 0
    float xv = 0.0f;
    if (g < 400) xv = xcol[(size_t)(d ? 31 : 0) * 800];
    __syncthreads();

    for (int s = 0; s < 32; s++) {
        const int t = d ? (31 - s) : s;
        // Prefetch next step's gate value (hides L2 latency behind matvec)
        float xn = 0.0f;
        if (s < 31 && g < 400) {
            const int tn = d ? (30 - s) : (s + 1);
            xn = xcol[(size_t)tn * 800];
        }
        if (g < 400) {
            float a0 = 0.f, a1 = 0.f, a2 = 0.f, a3 = 0.f;
#pragma unroll
            for (int k = 0; k < 100; k += 4) {
                float4 hv = *(const float4*)(h_s + k);
                a0 += wreg[k]     * hv.x;
                a1 += wreg[k + 1] * hv.y;
                a2 += wreg[k + 2] * hv.z;
                a3 += wreg[k + 3] * hv.w;
            }
            gates_s[g] = (xv + bias_r) + ((a0 + a1) + (a2 + a3));
        }
        __syncthreads();
        if (g < 100) {
            const bool valid = (t < len);
            const float iv = gates_s[g];
            const float fv = gates_s[100 + g];
            const float gv = gates_s[200 + g];
            const float ov = gates_s[300 + g];
            const float cn = sigm(fv) * c_r + sigm(iv) * tanh_f(gv);
            const float hn = sigm(ov) * tanh_f(cn);
            const float ho = valid ? hn : h_s[g];
            c_r = valid ? cn : c_r;
            out[(size_t)(b * 32 + t) * 200 + d * 100 + g] = valid ? hn : 0.0f;
            h_s[g] = ho;
        }
        xv = xn;
        __syncthreads();
    }
}

// ---------------------------------------------------------------------------
// enc[b][g] = (sum_t hA[b][t][g]) / len[b]
// ---------------------------------------------------------------------------
__global__ void enc_kernel(const int* __restrict__ lengths)
{
    const int b = blockIdx.x;
    const int g = threadIdx.x;
    if (g < 200) {
        float s = 0.0f;
#pragma unroll
        for (int t = 0; t < 32; t++) s += g_hA[(size_t)(b * 32 + t) * 200 + g];
        g_enc[b * 200 + g] = s / (float)lengths[b];
    }
}

// ---------------------------------------------------------------------------
// Cluster parser (8 CTAs).
//   rank 0 (leader): stack, feat, decision, cell update.
//   ranks 1..7: 72 Wt rows each (204-float padded rows, conflict-free
//   LDS.128); run the matvec SPECULATIVELY on every step, overlapped with
//   the leader's score/argmax. Leader PUSHES u into worker smem during the
//   feat gather; dec never crosses CTAs.
// Per step: A) leader gathers feat + pushes u  | sync | B) workers matvec
// (always) while leader computes decision      | sync | C) leader applies.
// ---------------------------------------------------------------------------
#define P_RPW     72
#define OFF_STACK 0                       // 256*200
#define OFF_FEAT  51200                   // 600
#define OFF_GAT   51800                   // 512 (500 used)
#define OFF_WA    52312                   // 1200
#define OFF_MISS  53512                   // 200
#define OFF_DEC   53712                   // 1 int (leader-local)
#define PAR_SMEM_FLOATS 53716
// worker-local aliases (same allocation, low offsets)
#define WOFF_WT   0                       // 72*204 = 14688
#define WOFF_BT   14688                   // 72
#define WOFF_UL   14760                   // 204 used 200; 14760*4 % 16 == 0

__device__ __forceinline__ uint32_t smem_addr_u32(const void* p) {
    uint32_t a;
    asm("{ .reg .u64 t; cvta.to.shared.u64 t, %1; cvt.u32.u64 %0, t; }"
        : "=r"(a) : "l"(p));
    return a;
}
__device__ __forceinline__ uint32_t mapa_rank(uint32_t local, int r) {
    uint32_t out;
    asm("mapa.shared::cluster.u32 %0, %1, %2;" : "=r"(out) : "r"(local), "r"(r));
    return out;
}
__device__ __forceinline__ void st_dsmem_f(uint32_t a, float v) {
    asm volatile("st.shared::cluster.f32 [%0], %1;" :: "r"(a), "f"(v) : "memory");
}
__device__ __forceinline__ void cluster_sync_all() {
    asm volatile("barrier.cluster.arrive.aligned;" ::: "memory");
    asm volatile("barrier.cluster.wait.aligned;"   ::: "memory");
}

__global__ __launch_bounds__(512, 1) __cluster_dims__(8, 1, 1)
void parser_kernel(
    const float* __restrict__ missing,
    const float* __restrict__ Wa, const float* __restrict__ ba,
    const float* __restrict__ Wt, const float* __restrict__ bt,
    float* __restrict__ out)
{
    extern __shared__ float sm[];
    const int t    = threadIdx.x;
    const int rank = blockIdx.x;
    __shared__ float ba_s[2];

    float* stack = sm + OFF_STACK;
    float* feat  = sm + OFF_FEAT;
    float* gat   = sm + OFF_GAT;
    float* wa_s  = sm + OFF_WA;
    float* mis_s = sm + OFF_MISS;

    int wbase = 0, wcnt = 0;
    if (rank == 0) {
        for (int i = t; i < 1200; i += 512) wa_s[i]  = Wa[i];
        for (int i = t; i < 200;  i += 512) mis_s[i] = missing[i];
        if (t < 2) ba_s[t] = ba[t];
    } else {
        wbase = (rank - 1) * P_RPW;
        wcnt  = min(P_RPW, 500 - wbase);
        for (int i = t; i < wcnt * 200; i += 512) {
            const int r = i / 200, k = i % 200;
            sm[WOFF_WT + r * 204 + k] = Wt[(size_t)(wbase + r) * 200 + k];
        }
        for (int i = t; i < wcnt; i += 512) sm[WOFF_BT + i] = bt[wbase + i];
    }
    __syncthreads();
    cluster_sync_all();

    int sp = 0, bp = 0;

    for (int step = 0; step < 2 * NSEQ - 1; step++) {
        // ---- Phase A: leader gathers feat; pushes u=[h1;h2] into workers
        if (rank == 0) {
            for (int i = t; i < 600; i += 512) {
                float v;
                if (i < 200)      v = (sp >= 2) ? stack[(sp - 2) * 200 + i]         : mis_s[i];
                else if (i < 400) v = (sp >= 1) ? stack[(sp - 1) * 200 + (i - 200)] : mis_s[i - 200];
                else              v = (bp < NSEQ) ? g_enc[(size_t)bp * 200 + (i - 400)] : mis_s[i - 400];
                feat[i] = v;
                int ui = -1;
                if (i < 100)                   ui = i;          // h1
                else if (i >= 200 && i < 300)  ui = i - 100;    // h2
                if (ui >= 0) {
                    const uint32_t la = smem_addr_u32(&sm[WOFF_UL + ui]);
#pragma unroll
                    for (int r = 1; r < 8; r++) st_dsmem_f(mapa_rank(la, r), v);
                }
            }
        }

        cluster_sync_all();   // releases feat + remote u pushes

        // ---- Phase B: workers speculative matvec || leader decision
        if (rank != 0) {
            if (t < wcnt) {
                const float* wr = sm + WOFF_WT + t * 204;
                const float* ul = sm + WOFF_UL;
                float a0 = 0.f, a1 = 0.f, a2 = 0.f, a3 = 0.f;
#pragma unroll
                for (int k = 0; k < 200; k += 4) {
                    const float4 wv = *(const float4*)(wr + k);
                    const float4 uv = *(const float4*)(ul + k);
                    a0 += wv.x * uv.x; a1 += wv.y * uv.y;
                    a2 += wv.z * uv.z; a3 += wv.w * uv.w;
                }
                const float acc = sm[WOFF_BT + t] + ((a0 + a1) + (a2 + a3));
                st_dsmem_f(mapa_rank(smem_addr_u32(&gat[wbase + t]), 0), acc);
            }
        } else {
            if (t < 32) {
                float a0 = 0.0f, a1 = 0.0f;
                for (int k = t; k < 600; k += 32) {
                    const float f = feat[k];
                    a0 += wa_s[k] * f;
                    a1 += wa_s[600 + k] * f;
                }
#pragma unroll
                for (int o = 16; o > 0; o >>= 1) {
                    a0 += __shfl_xor_sync(0xffffffffu, a0, o);
                    a1 += __shfl_xor_sync(0xffffffffu, a1, o);
                }
                if (t == 0) {
                    const float m0 = (bp < NSEQ) ? (a0 + ba_s[0]) : -1e30f;
                    const float m1 = (sp >= 2)   ? (a1 + ba_s[1]) : -1e30f;
                    ((int*)sm)[OFF_DEC] = (m0 >= m1) ? 1 : 0;   // argmax tie -> shift
                }
            }
        }

        cluster_sync_all();   // gates + dec visible

        // ---- Phase C: leader applies the chosen action
        if (rank == 0) {
            const int isShift = ((const int*)sm)[OFF_DEC];
            if (isShift) {
                int pos = sp; if (pos > NSEQ - 1) pos = NSEQ - 1;
                if (t < 200) stack[pos * 200 + t] = feat[400 + t];
                sp += 1; bp += 1;
            } else {
                if (t < 100) {
                    const float iv = gat[t];
                    const float f1 = gat[100 + t];
                    const float f2 = gat[200 + t];
                    const float ov = gat[300 + t];
                    const float uu = gat[400 + t];
                    const float c1 = feat[100 + t];   // s1 cell half
                    const float c2 = feat[300 + t];   // s0 cell half
                    const float c  = sigm(f1) * c1 + sigm(f2) * c2 + sigm(iv) * tanh_f(uu);
                    const float h  = sigm(ov) * tanh_f(c);
                    int pos = sp - 2; if (pos < 0) pos = 0;
                    stack[pos * 200 + t]       = h;
                    stack[pos * 200 + 100 + t] = c;
                }
                sp -= 1;
            }
            __syncthreads();   // stack consistent before next gather
        }
    }

    if (rank == 0 && t < 200) out[t] = stack[t];
}

// ---------------------------------------------------------------------------
// Host launcher
// ---------------------------------------------------------------------------
extern "C" void kernel_launch(void* const* d_in, const int* in_sizes, int n_in,
                              void* d_out, int out_size)
{
    const int*   tokens  = (const int*)  d_in[0];
    const int*   lengths = (const int*)  d_in[1];
    const float* emb     = (const float*)d_in[2];
    const float* Wih_l0  = (const float*)d_in[3];
    const float* Whh_l0  = (const float*)d_in[4];
    const float* b_l0    = (const float*)d_in[5];
    const float* Wih_l12 = (const float*)d_in[6];
    const float* Whh_l12 = (const float*)d_in[7];
    const float* b_l12   = (const float*)d_in[8];
    const float* missing = (const float*)d_in[9];
    const float* Wa      = (const float*)d_in[10];
    const float* ba      = (const float*)d_in[11];
    const float* Wt      = (const float*)d_in[12];
    const float* bt      = (const float*)d_in[13];
    float* out = (float*)d_out;

    const size_t parser_smem = PAR_SMEM_FLOATS * sizeof(float);  // 214,864 B
    cudaFuncSetAttribute(parser_kernel, cudaFuncAttributeMaxDynamicSharedMemorySize,
                         (int)parser_smem);

    const dim3 gg(MTOT / 128, (GNN + 127) / 128);   // (64, 7)

    sgemm_tn<<<gg, 256>>>(0, Wih_l0, 300, tokens, emb);
    lstm_rec<<<2 * NSEQ, 416>>>(Whh_l0, b_l0, lengths, 0);

    sgemm_tn<<<gg, 256>>>(1, Wih_l12, 200, nullptr, nullptr);
    lstm_rec<<<2 * NSEQ, 416>>>(Whh_l12, b_l12, lengths, 1);

    sgemm_tn<<<gg, 256>>>(2, Wih_l12 + 2 * 400 * 200, 200, nullptr, nullptr);
    lstm_rec<<<2 * NSEQ, 416>>>(Whh_l12 + 2 * 400 * 100, b_l12 + 800, lengths, 0);

    enc_kernel<<<NSEQ, 256>>>(lengths);

    parser_kernel<<<8, 512, parser_smem>>>(missing, Wa, ba, Wt, bt, out);
}